// round 17
// baseline (speedup 1.0000x reference)
#include <cuda_runtime.h>
#include <cuda_fp16.h>
#include <cstdint>
#include <math.h>

#define C_DIM 256
#define N_DIM 4096
#define B_DIM 2
#define HEADS 8
#define BCN (B_DIM * C_DIM * N_DIM)   // 2097152

// ---------------- scratch ----------------
__device__ float g_scale[B_DIM * C_DIM];
__device__ float g_shift[B_DIM * C_DIM];
__device__ float g_psum[128], g_psum2[128];
__device__ __align__(16) __half g_wh[4 * 65536];   // wq,wk,wv,wo fp16
__device__ __align__(16) __half g_xh[BCN];         // normalized x fp16 [b][c][n]
__device__ __align__(16) __half g_qnd[BCN];        // [b*8+h][n][32]
__device__ __align__(16) __half g_knd[BCN];        // [b*8+h][n][32]
__device__ __align__(16) __half g_vdn[BCN];        // [b][c][n]
__device__ __align__(16) __half g_attnh[BCN];      // attention out fp16 [b][c][n]

// ---------------- helpers ----------------
__device__ __forceinline__ uint32_t smem_u32(const void* p) {
    uint32_t a;
    asm("{ .reg .u64 t; cvta.to.shared.u64 t, %1; cvt.u32.u64 %0, t; }" : "=r"(a) : "l"(p));
    return a;
}
__device__ __forceinline__ uint32_t packh(float lo, float hi) {
    uint32_t r; asm("cvt.rn.f16x2.f32 %0, %1, %2;" : "=r"(r) : "f"(hi), "f"(lo)); return r;
}
#define H2EXP(x) asm("ex2.approx.f16x2 %0, %0;" : "+r"(x))

#define CP16(dst, src) asm volatile("cp.async.cg.shared.global [%0], [%1], 16;" :: "r"(dst), "l"(src))
#define CP_COMMIT()    asm volatile("cp.async.commit_group;" ::: "memory")
#define CP_WAIT(n)     asm volatile("cp.async.wait_group %0;" :: "n"(n) : "memory")

#define LDSM4(r0, r1, r2, r3, a) \
    asm volatile("ldmatrix.sync.aligned.m8n8.x4.shared.b16 {%0,%1,%2,%3}, [%4];" \
        : "=r"(r0), "=r"(r1), "=r"(r2), "=r"(r3) : "r"(a))
#define LDSM4T(r0, r1, r2, r3, a) \
    asm volatile("ldmatrix.sync.aligned.m8n8.x4.trans.shared.b16 {%0,%1,%2,%3}, [%4];" \
        : "=r"(r0), "=r"(r1), "=r"(r2), "=r"(r3) : "r"(a))

#define MMA_F16(d0, d1, a0, a1, a2, a3, b0, b1, c0, c1) \
    asm volatile("mma.sync.aligned.m16n8k16.row.col.f16.f16.f16.f16 " \
        "{%0,%1},{%2,%3,%4,%5},{%6,%7},{%8,%9};" \
        : "=r"(d0), "=r"(d1) \
        : "r"(a0), "r"(a1), "r"(a2), "r"(a3), "r"(b0), "r"(b1), "r"(c0), "r"(c1))

#define MMA_F32(D, a0, a1, a2, a3, b0, b1) \
    asm volatile("mma.sync.aligned.m16n8k16.row.col.f32.f16.f16.f32 " \
        "{%0,%1,%2,%3},{%4,%5,%6,%7},{%8,%9},{%0,%1,%2,%3};" \
        : "+f"((D)[0]), "+f"((D)[1]), "+f"((D)[2]), "+f"((D)[3]) \
        : "r"(a0), "r"(a1), "r"(a2), "r"(a3), "r"(b0), "r"(b1))

// ---------------- GN phase A: 128 partial-reduce CTAs + 64 wconv CTAs ----------------
__global__ __launch_bounds__(256) void gnA_kernel(
    const float* __restrict__ x,
    const float* __restrict__ wq, const float* __restrict__ wk,
    const float* __restrict__ wv, const float* __restrict__ wo,
    float* __restrict__ psum, float* __restrict__ psum2, __half* __restrict__ wh)
{
    if (blockIdx.x < 128) {
        int cta = blockIdx.x;
        const float* p = x + (size_t)cta * 16384;
        float s = 0.f, s2 = 0.f;
        #pragma unroll 4
        for (int i = threadIdx.x; i < 4096; i += 256) {
            float4 v = reinterpret_cast<const float4*>(p)[i];
            s  += v.x + v.y + v.z + v.w;
            s2 += v.x * v.x + v.y * v.y + v.z * v.z + v.w * v.w;
        }
        __shared__ float rs[256], rs2[256];
        rs[threadIdx.x] = s; rs2[threadIdx.x] = s2;
        __syncthreads();
        for (int st = 128; st; st >>= 1) {
            if (threadIdx.x < st) {
                rs[threadIdx.x]  += rs[threadIdx.x + st];
                rs2[threadIdx.x] += rs2[threadIdx.x + st];
            }
            __syncthreads();
        }
        if (threadIdx.x == 0) { psum[cta] = rs[0]; psum2[cta] = rs2[0]; }
    } else {
        const float* srcs[4] = {wq, wk, wv, wo};
        int base = (blockIdx.x - 128) * 1024 + threadIdx.x;  // over 65536 float4
        #pragma unroll
        for (int r = 0; r < 4; r++) {
            int i = base + r * 256;
            int which = i >> 14, off = i & 16383;
            float4 v = reinterpret_cast<const float4*>(srcs[which])[off];
            uint2 pk;
            pk.x = packh(v.x, v.y); pk.y = packh(v.z, v.w);
            reinterpret_cast<uint2*>(g_wh + (size_t)which * 65536)[off] = pk;
        }
    }
}

// ---------------- normalized x -> fp16 (GN finalize folded in) ----------------
// Each CTA covers 256 float4 = quarter of one channel row -> one (b,c) pair.
__global__ __launch_bounds__(256) void xconv_kernel(
    const float* __restrict__ x, const float* __restrict__ psum,
    const float* __restrict__ psum2, const float* __restrict__ gw,
    const float* __restrict__ gb, __half* __restrict__ xh)
{
    int i = blockIdx.x * 256 + threadIdx.x;      // over 524288 float4
    int c = (blockIdx.x >> 2) & 255, b = blockIdx.x >> 10;
    int g = c >> 5;
    int pbase = b * 64 + g * 8;
    float s = 0.f, s2 = 0.f;
    #pragma unroll
    for (int k = 0; k < 8; k++) { s += psum[pbase + k]; s2 += psum2[pbase + k]; }
    float m = s * (1.f / 131072.f);
    float var = s2 * (1.f / 131072.f) - m * m;
    float rstd = rsqrtf(var + 1e-5f);
    float sc = gw[c] * rstd;
    float sh = gb[c] - m * sc;

    float4 v = reinterpret_cast<const float4*>(x)[i];
    uint2 pk;
    pk.x = packh(fmaf(v.x, sc, sh), fmaf(v.y, sc, sh));
    pk.y = packh(fmaf(v.z, sc, sh), fmaf(v.w, sc, sh));
    reinterpret_cast<uint2*>(xh)[i] = pk;
}

// ================= HMMA GEMM core (128o x 128n, K=256), single-sync pipeline =====
struct GemmAcc { float a[2][8][4]; };

__device__ __forceinline__ void hgemm_core(
    const __half* __restrict__ Wp, const __half* __restrict__ Xp,
    uint32_t sb, int n0, int tid, int w, int lane, int warp_o, int warp_n,
    GemmAcc& A)
{
    auto prefW = [&](int k0, int buf) {
        #pragma unroll
        for (int r = 0; r < 2; r++) {
            int idx = tid + r * 256;
            int o = idx >> 2, seg = idx & 3;
            CP16(sb + buf * 10240 + o * 80 + seg * 16,
                 Wp + (size_t)o * 256 + k0 + seg * 8);
        }
    };
    auto prefX = [&](int k0, int buf) {
        #pragma unroll
        for (int r = 0; r < 2; r++) {
            int idx = tid + r * 256;
            int k = idx >> 4, seg = idx & 15;
            CP16(sb + 20480 + buf * 8704 + k * 272 + seg * 16,
                 Xp + (size_t)(k0 + k) * N_DIM + n0 + seg * 8);
        }
    };
    prefW(0, 0); prefX(0, 0); CP_COMMIT();
    for (int kc = 0; kc < 8; kc++) {
        int buf = kc & 1;
        CP_WAIT(0);
        __syncthreads();
        if (kc < 7) { prefW((kc + 1) * 32, buf ^ 1); prefX((kc + 1) * 32, buf ^ 1); CP_COMMIT(); }
        uint32_t wb = sb + buf * 10240;
        uint32_t xb = sb + 20480 + buf * 8704;
        #pragma unroll
        for (int kk = 0; kk < 2; kk++) {
            uint32_t a[2][4];
            #pragma unroll
            for (int m = 0; m < 2; m++) {
                uint32_t addr = wb + (warp_o + m * 16 + (lane & 15)) * 80 + kk * 32 + ((lane & 16) ? 16 : 0);
                LDSM4(a[m][0], a[m][1], a[m][2], a[m][3], addr);
            }
            #pragma unroll
            for (int j = 0; j < 4; j++) {
                uint32_t b0, b1, b2, b3;
                uint32_t addr = xb + (kk * 16 + (lane & 15)) * 272 + (warp_n + j * 16 + ((lane >> 4) * 8)) * 2;
                LDSM4T(b0, b1, b2, b3, addr);
                MMA_F32(A.a[0][2*j],   a[0][0], a[0][1], a[0][2], a[0][3], b0, b1);
                MMA_F32(A.a[0][2*j+1], a[0][0], a[0][1], a[0][2], a[0][3], b2, b3);
                MMA_F32(A.a[1][2*j],   a[1][0], a[1][1], a[1][2], a[1][3], b0, b1);
                MMA_F32(A.a[1][2*j+1], a[1][0], a[1][1], a[1][2], a[1][3], b2, b3);
            }
        }
    }
    __syncthreads();   // protect smem reuse in epilogues
}

// ---------------- fused QKV GEMM: grid (32, 6, 2) ----------------
__global__ __launch_bounds__(256) void qkv_gemm_kernel(
    const __half* __restrict__ Wh,
    const float* __restrict__ bq, const float* __restrict__ bk, const float* __restrict__ bv,
    const __half* __restrict__ Xh,
    __half* __restrict__ qnd, __half* __restrict__ knd, __half* __restrict__ vdn,
    float qs)
{
    __shared__ __align__(16) char sm[37888];
    const int n0 = blockIdx.x * 128;
    const int my = blockIdx.y;
    const int mat = my >> 1, otile = my & 1;
    const int b = blockIdx.z;
    const int tid = threadIdx.x, w = tid >> 5, lane = tid & 31;
    const int warp_o = (w >> 1) * 32, warp_n = (w & 1) * 64;
    const uint32_t sb = smem_u32(sm);

    const float* bias = (mat == 0) ? bq : (mat == 1) ? bk : bv;
    const float outscale = (mat == 0) ? qs : 1.0f;
    __half* Yh = (mat == 0) ? qnd : (mat == 1) ? knd : vdn;

    GemmAcc A = {};
    hgemm_core(Wh + (size_t)mat * 65536 + (size_t)otile * 128 * 256,
               Xh + (size_t)b * C_DIM * N_DIM, sb, n0, tid, w, lane, warp_o, warp_n, A);

    const int rr = lane >> 2, cc = (lane & 3) * 2;
    if (mat == 2) {
        const size_t ybase = (size_t)b * C_DIM * N_DIM;
        #pragma unroll
        for (int m = 0; m < 2; m++) {
            #pragma unroll
            for (int j = 0; j < 8; j++) {
                int o = otile * 128 + warp_o + m * 16 + rr;
                int n = n0 + warp_n + j * 8 + cc;
                float bo = bias[o], bo8 = bias[o + 8];
                *reinterpret_cast<uint32_t*>(Yh + ybase + (size_t)o * N_DIM + n) =
                    packh(A.a[m][j][0] + bo, A.a[m][j][1] + bo);
                *reinterpret_cast<uint32_t*>(Yh + ybase + (size_t)(o + 8) * N_DIM + n) =
                    packh(A.a[m][j][2] + bo8, A.a[m][j][3] + bo8);
            }
        }
    } else {
        // Q/K: fp16 [(b*8+o/32)][n][o%32] via smem transpose staging
        char* stg = sm + w * 4224;
        const int obase = otile * 128 + warp_o;
        #pragma unroll
        for (int m = 0; m < 2; m++) {
            #pragma unroll
            for (int j = 0; j < 8; j++) {
                int row = m * 16 + rr;
                int col = j * 8 + cc;
                float bo = bias[obase + row], bo8 = bias[obase + row + 8];
                *reinterpret_cast<uint32_t*>(stg + row * 132 + col * 2) =
                    packh((A.a[m][j][0] + bo) * outscale, (A.a[m][j][1] + bo) * outscale);
                *reinterpret_cast<uint32_t*>(stg + (row + 8) * 132 + col * 2) =
                    packh((A.a[m][j][2] + bo8) * outscale, (A.a[m][j][3] + bo8) * outscale);
            }
        }
        __syncwarp();
        int hh = obase >> 5;
        __half* qp = Yh + ((size_t)(b * HEADS + hh) * N_DIM + n0 + warp_n) * 32;
        const ushort* sh = reinterpret_cast<const ushort*>(stg);
        int dl2 = lane & 15;
        #pragma unroll
        for (int i = 0; i < 32; i++) {
            int nloc = i * 2 + (lane >> 4);
            uint32_t h0 = sh[(2 * dl2) * 66 + nloc];
            uint32_t h1 = sh[(2 * dl2 + 1) * 66 + nloc];
            *reinterpret_cast<uint32_t*>(reinterpret_cast<char*>(qp) + (size_t)nloc * 64 + dl2 * 4) =
                h0 | (h1 << 16);
        }
    }
}

// ---------------- out-proj GEMM: fp32 + bias + residual ----------------
__global__ __launch_bounds__(256) void oproj_kernel(
    const __half* __restrict__ Wh, const float* __restrict__ bias,
    const __half* __restrict__ Xh, const float* __restrict__ resid,
    float* __restrict__ Yf)
{
    __shared__ __align__(16) char sm[37888];
    const int n0 = blockIdx.x * 128;
    const int otile = blockIdx.y;
    const int b = blockIdx.z;
    const int tid = threadIdx.x, w = tid >> 5, lane = tid & 31;
    const int warp_o = (w >> 1) * 32, warp_n = (w & 1) * 64;
    const uint32_t sb = smem_u32(sm);

    GemmAcc A = {};
    hgemm_core(Wh + (size_t)otile * 128 * 256,
               Xh + (size_t)b * C_DIM * N_DIM, sb, n0, tid, w, lane, warp_o, warp_n, A);

    const int rr = lane >> 2, cc = (lane & 3) * 2;
    const size_t ybase = (size_t)b * C_DIM * N_DIM;
    #pragma unroll
    for (int m = 0; m < 2; m++) {
        #pragma unroll
        for (int j = 0; j < 8; j++) {
            int o = otile * 128 + warp_o + m * 16 + rr;
            int n = n0 + warp_n + j * 8 + cc;
            float bo = bias[o], bo8 = bias[o + 8];
            size_t off = ybase + (size_t)o * N_DIM + n;
            float2 r0 = *reinterpret_cast<const float2*>(resid + off);
            float2 r1 = *reinterpret_cast<const float2*>(resid + off + 8 * N_DIM);
            float2 v0 = {A.a[m][j][0] + bo + r0.x, A.a[m][j][1] + bo + r0.y};
            float2 v1 = {A.a[m][j][2] + bo8 + r1.x, A.a[m][j][3] + bo8 + r1.y};
            *reinterpret_cast<float2*>(Yf + off) = v0;
            *reinterpret_cast<float2*>(Yf + off + 8 * N_DIM) = v1;
        }
    }
}

// ---------------- flash attention: 256-q CTA, 512 threads ----------------
#define FSMQ  0
#define FSMK0 20480
#define FSMK1 30720
#define FSMV0 40960
#define FSMV1 49664
#define FSM_TOTAL 58368

__global__ __launch_bounds__(512) void flash_mma_kernel(
    const __half* __restrict__ Qg_, const __half* __restrict__ Kg_,
    const __half* __restrict__ Vg_, __half* __restrict__ aout)
{
    extern __shared__ __align__(16) char smem[];
    const int q0 = blockIdx.x * 256;
    const int h = blockIdx.y, b = blockIdx.z;
    const int tid = threadIdx.x;
    const int w = tid >> 5, lane = tid & 31;
    const uint32_t sb = smem_u32(smem);

    const int bh = b * HEADS + h;
    const __half* Qg = Qg_ + (size_t)bh * N_DIM * 32;
    const __half* Kg = Kg_ + (size_t)bh * N_DIM * 32;
    const __half* Vg = Vg_ + (size_t)(b * C_DIM + h * 32) * N_DIM;

    for (int c = tid; c < 1024; c += 512) {
        int row = c >> 2, seg = c & 3;
        uint4 v = *reinterpret_cast<const uint4*>(Qg + (size_t)(q0 + row) * 32 + seg * 8);
        *reinterpret_cast<uint4*>(smem + FSMQ + row * 80 + seg * 16) = v;
    }

    auto prefK = [&](int m0, uint32_t base) {
        int row = tid >> 2, seg = tid & 3;
        CP16(sb + base + row * 80 + seg * 16,
             Kg + (size_t)(m0 + row) * 32 + seg * 8);
    };
    auto prefV = [&](int m0, uint32_t base) {
        int d = tid >> 4, seg = tid & 15;
        CP16(sb + base + d * 272 + seg * 16,
             Vg + (size_t)d * N_DIM + m0 + seg * 8);
    };
    prefK(0, FSMK0);
    prefV(0, FSMV0);
    CP_COMMIT();
    __syncthreads();

    uint32_t QA[2][4];
    {
        uint32_t qaddr = sb + FSMQ + (16 * w + (lane & 15)) * 80 + ((lane & 16) ? 16 : 0);
        LDSM4(QA[0][0], QA[0][1], QA[0][2], QA[0][3], qaddr);
        LDSM4(QA[1][0], QA[1][1], QA[1][2], QA[1][3], qaddr + 32);
    }

    const uint32_t rowoff_k = ((lane & 7) + ((lane & 16) ? 8 : 0)) * 80 + ((lane & 8) ? 16 : 0);
    const uint32_t rowoff_v = ((lane & 7) + ((lane & 16) ? 8 : 0)) * 272 + ((lane & 8) ? 16 : 0);

    float O[4][4] = {};
    float rsum0 = 0.f, rsum8 = 0.f;

    for (int it = 0; it < 32; it++) {
        const int cur = it & 1;
        CP_WAIT(0);
        __syncthreads();
        if (it + 1 < 32) {
            prefK(128 * (it + 1), cur ? FSMK0 : FSMK1);
            prefV(128 * (it + 1), cur ? FSMV0 : FSMV1);
            CP_COMMIT();
        }

        const uint32_t kb = sb + (cur ? FSMK1 : FSMK0);
        const uint32_t vb = sb + (cur ? FSMV1 : FSMV0);

        uint32_t S[16][2];
        #pragma unroll
        for (int jp = 0; jp < 8; jp++) {
            uint32_t b0, b1, b2, b3;
            uint32_t base = kb + jp * 1280 + rowoff_k;
            LDSM4(b0, b1, b2, b3, base);
            const uint32_t z = 0;
            MMA_F16(S[2*jp][0],   S[2*jp][1],   QA[0][0], QA[0][1], QA[0][2], QA[0][3], b0, b1, z, z);
            MMA_F16(S[2*jp+1][0], S[2*jp+1][1], QA[0][0], QA[0][1], QA[0][2], QA[0][3], b2, b3, z, z);
            LDSM4(b0, b1, b2, b3, base + 32);
            MMA_F16(S[2*jp][0],   S[2*jp][1],   QA[1][0], QA[1][1], QA[1][2], QA[1][3], b0, b1, S[2*jp][0],   S[2*jp][1]);
            MMA_F16(S[2*jp+1][0], S[2*jp+1][1], QA[1][0], QA[1][1], QA[1][2], QA[1][3], b2, b3, S[2*jp+1][0], S[2*jp+1][1]);
        }
        #pragma unroll
        for (int j = 0; j < 16; j++) { H2EXP(S[j][0]); H2EXP(S[j][1]); }

        // rowsum on the FMA pipe (replaces the ones-matrix MMA)
        #pragma unroll
        for (int j = 0; j < 16; j++) {
            float2 a = __half22float2(*reinterpret_cast<__half2*>(&S[j][0]));
            float2 c = __half22float2(*reinterpret_cast<__half2*>(&S[j][1]));
            rsum0 += a.x + a.y;
            rsum8 += c.x + c.y;
        }

        #pragma unroll
        for (int kk = 0; kk < 8; kk++) {
            uint32_t a0 = S[2*kk][0], a1 = S[2*kk][1], a2 = S[2*kk+1][0], a3 = S[2*kk+1][1];
            #pragma unroll
            for (int nbp = 0; nbp < 2; nbp++) {
                uint32_t v0, v1, v2, v3;
                LDSM4(v0, v1, v2, v3, vb + nbp * 4352 + rowoff_v + kk * 32);
                MMA_F32(O[2*nbp],   a0, a1, a2, a3, v0, v1);
                MMA_F32(O[2*nbp+1], a0, a1, a2, a3, v2, v3);
            }
        }
    }
    __syncthreads();   // all PV reads done before Osm overwrites K/V regions

    // quad-lane reduction: lanes lane&3 of a row group hold disjoint columns
    rsum0 += __shfl_xor_sync(0xffffffffu, rsum0, 1);
    rsum0 += __shfl_xor_sync(0xffffffffu, rsum0, 2);
    rsum8 += __shfl_xor_sync(0xffffffffu, rsum8, 1);
    rsum8 += __shfl_xor_sync(0xffffffffu, rsum8, 2);
    float inv0 = 1.f / rsum0, inv8 = 1.f / rsum8;

    float* Osm = reinterpret_cast<float*>(smem + FSMK0);  // [32 d][260]
    int row = lane >> 2;
    int qc = 16 * w + row;
    #pragma unroll
    for (int nb = 0; nb < 4; nb++) {
        int d0 = 8 * nb + 2 * (lane & 3);
        Osm[d0 * 260 + qc]           = O[nb][0] * inv0;
        Osm[(d0 + 1) * 260 + qc]     = O[nb][1] * inv0;
        Osm[d0 * 260 + qc + 8]       = O[nb][2] * inv8;
        Osm[(d0 + 1) * 260 + qc + 8] = O[nb][3] * inv8;
    }
    __syncthreads();
    __half* outp = aout + (size_t)(b * C_DIM + h * 32) * N_DIM + q0;
    for (int c = tid; c < 2048; c += 512) {
        int d = c >> 6, qq = (c & 63) * 4;
        float4 v = *reinterpret_cast<const float4*>(&Osm[d * 260 + qq]);
        uint2 pk;
        pk.x = packh(v.x, v.y); pk.y = packh(v.z, v.w);
        *reinterpret_cast<uint2*>(outp + (size_t)d * N_DIM + qq) = pk;
    }
}

// ---------------- launch ----------------
extern "C" void kernel_launch(void* const* d_in, const int* in_sizes, int n_in,
                              void* d_out, int out_size)
{
    const float* x    = (const float*)d_in[0];
    const float* gn_w = (const float*)d_in[1];
    const float* gn_b = (const float*)d_in[2];
    const float* wq   = (const float*)d_in[3];
    const float* bq   = (const float*)d_in[4];
    const float* wk   = (const float*)d_in[5];
    const float* bk   = (const float*)d_in[6];
    const float* wv   = (const float*)d_in[7];
    const float* bv   = (const float*)d_in[8];
    const float* wo   = (const float*)d_in[9];
    const float* bo   = (const float*)d_in[10];
    float* out = (float*)d_out;

    float *ps, *ps2;
    __half *wh, *xh, *qnd, *knd, *vdn, *attnh;
    cudaGetSymbolAddress((void**)&ps,    g_psum);
    cudaGetSymbolAddress((void**)&ps2,   g_psum2);
    cudaGetSymbolAddress((void**)&wh,    g_wh);
    cudaGetSymbolAddress((void**)&xh,    g_xh);
    cudaGetSymbolAddress((void**)&qnd,   g_qnd);
    cudaGetSymbolAddress((void**)&knd,   g_knd);
    cudaGetSymbolAddress((void**)&vdn,   g_vdn);
    cudaGetSymbolAddress((void**)&attnh, g_attnh);

    cudaFuncSetAttribute(flash_mma_kernel, cudaFuncAttributeMaxDynamicSharedMemorySize, FSM_TOTAL);

    gnA_kernel<<<192, 256>>>(x, wq, wk, wv, wo, ps, ps2, wh);
    xconv_kernel<<<2048, 256>>>(x, ps, ps2, gn_w, gn_b, xh);

    const float qs = 0.2550466864771404f;   // log2(e)/sqrt(32)
    dim3 qkvgrid(32, 6, 2);
    qkv_gemm_kernel<<<qkvgrid, 256>>>(wh, bq, bk, bv, xh, qnd, knd, vdn, qs);

    dim3 fgrid(16, HEADS, B_DIM);
    flash_mma_kernel<<<fgrid, 512, FSM_TOTAL>>>(qnd, knd, vdn, attnh);

    dim3 ogrid(32, 2, 2);
    oproj_kernel<<<ogrid, 256>>>(wh + 196608, bo, attnh, x, out);
}